// round 4
// baseline (speedup 1.0000x reference)
#include <cuda_runtime.h>

#define BB 4
#define CC 64
#define NN 4096
#define KTOP 20

// ---- scratch (static __device__ globals; runtime allocation is forbidden) ----
__device__ float g_xt[BB * NN * CC];                 // (B,N,C)  4 MB
__device__ float g_sq[BB * NN];                      // ||x||^2
__device__ float g_pd[(size_t)BB * NN * NN];         // pairwise "distance" 268 MB
__device__ int   g_idx[BB * NN * KTOP];              // top-k indices
__device__ float g_att[BB * NN * CC];                // attention output (B,N,C)
__device__ int   g_boolmode;                         // 0 = 1-byte bool, 1 = int32

// ---------------------------------------------------------------------------
// Detect how the bool mask is packed. If local_idx was delivered as int32,
// bytes at offsets %4 != 0 are all zero. For a 1-byte bool array of ~50% ones
// that event has probability ~2^-12288. Deterministic.
// ---------------------------------------------------------------------------
__global__ void detect_bool_kernel(const unsigned char* __restrict__ loc) {
    __shared__ int s;
    if (threadIdx.x == 0) s = 0;
    __syncthreads();
    int any = 0;
    for (int i = threadIdx.x; i < BB * NN; i += blockDim.x)
        if ((i & 3) != 0 && loc[i] != 0) any = 1;
    if (any) atomicOr(&s, 1);
    __syncthreads();
    if (threadIdx.x == 0) g_boolmode = s ? 0 : 1;
}

// ---------------------------------------------------------------------------
// Transpose x (B,C,N) -> g_xt (B,N,C)
// ---------------------------------------------------------------------------
__global__ void transpose_kernel(const float* __restrict__ x) {
    __shared__ float tile[32][33];
    int b = blockIdx.z, c0 = blockIdx.y * 32, n0 = blockIdx.x * 32;
    #pragma unroll
    for (int i = threadIdx.y; i < 32; i += 8)
        tile[i][threadIdx.x] =
            x[((size_t)(b * CC + c0 + i)) * NN + n0 + threadIdx.x];
    __syncthreads();
    #pragma unroll
    for (int i = threadIdx.y; i < 32; i += 8)
        g_xt[((size_t)(b * NN + n0 + i)) * CC + c0 + threadIdx.x] =
            tile[threadIdx.x][i];
}

// ---------------------------------------------------------------------------
// sq[b,n] = sum_c x[b,c,n]^2
// BITWISE-MATCH the XLA GPU *column reduction* of sum(x*x, axis=1) on
// (B, 64, N): thread y strides the reduce dim by the tile height (32):
//     p_y = fadd(fmul(x[y],x[y]), fmul(x[y+32],x[y+32]))
// then a shfl_down halving tree over the 32 partials (offsets 16,8,4,2,1),
// each add individually rounded. sq_j enters every top-k comparison; its
// bits must match the reference or near-tie neighbor selections flip.
// One warp per (b,n).
// ---------------------------------------------------------------------------
__global__ void sq_kernel(const float* __restrict__ x) {
    int gw   = (blockIdx.x * blockDim.x + threadIdx.x) >> 5;  // (b,n) id
    int lane = threadIdx.x & 31;
    if (gw >= BB * NN) return;
    int b = gw >> 12;
    int n = gw & (NN - 1);
    const float* xb = x + (size_t)b * CC * NN + n;

    float v0 = xb[(size_t)lane * NN];
    float v1 = xb[(size_t)(lane + 32) * NN];
    float p  = __fadd_rn(__fmul_rn(v0, v0), __fmul_rn(v1, v1));
    p = __fadd_rn(p, __shfl_down_sync(0xffffffffu, p, 16));
    p = __fadd_rn(p, __shfl_down_sync(0xffffffffu, p, 8));
    p = __fadd_rn(p, __shfl_down_sync(0xffffffffu, p, 4));
    p = __fadd_rn(p, __shfl_down_sync(0xffffffffu, p, 2));
    p = __fadd_rn(p, __shfl_down_sync(0xffffffffu, p, 1));
    if (lane == 0) g_sq[gw] = p;
}

// ---------------------------------------------------------------------------
// Pairwise distance GEMM: pd[b,i,j] = 2*dot(x_i, x_j) - sq_i - sq_j
// 128x128 tile per block, K=64 in two 32-chunks, 8x8 per thread.
// Inner product: single-accumulator fma chain ascending c = 0..63 — the
// association cublas sgemm / Eigen gebp use. 2*acc is exact, epilogue
// rounded per-op: ((2*acc - sqi) - sqj), matching the XLA elementwise fusion.
// ---------------------------------------------------------------------------
__global__ void __launch_bounds__(256) gemm_kernel(const float* __restrict__ x) {
    __shared__ float As[32][128];
    __shared__ float Bs[32][128];
    int b  = blockIdx.z;
    int ib = blockIdx.y << 7;
    int jb = blockIdx.x << 7;
    int tid = threadIdx.x;
    int tx = tid & 15, ty = tid >> 4;

    const float* xb = x + (size_t)b * CC * NN;

    float acc[8][8];
    #pragma unroll
    for (int i = 0; i < 8; ++i)
        #pragma unroll
        for (int j = 0; j < 8; ++j) acc[i][j] = 0.f;

    for (int k0 = 0; k0 < CC; k0 += 32) {
        if (k0) __syncthreads();
        #pragma unroll
        for (int u = 0; u < 4; ++u) {
            int idx = tid + (u << 8);          // 0..1023 float4 slots
            int c = idx >> 5;                  // 0..31
            int p = (idx & 31) << 2;           // 0..124
            *(float4*)&As[c][p] = *(const float4*)&xb[(size_t)(k0 + c) * NN + ib + p];
            *(float4*)&Bs[c][p] = *(const float4*)&xb[(size_t)(k0 + c) * NN + jb + p];
        }
        __syncthreads();
        #pragma unroll
        for (int kk = 0; kk < 32; ++kk) {
            float4 a0 = *(float4*)&As[kk][(ty << 2)];
            float4 a1 = *(float4*)&As[kk][64 + (ty << 2)];
            float4 b0 = *(float4*)&Bs[kk][(tx << 2)];
            float4 b1 = *(float4*)&Bs[kk][64 + (tx << 2)];
            float a[8]  = {a0.x, a0.y, a0.z, a0.w, a1.x, a1.y, a1.z, a1.w};
            float bv[8] = {b0.x, b0.y, b0.z, b0.w, b1.x, b1.y, b1.z, b1.w};
            #pragma unroll
            for (int i = 0; i < 8; ++i)
                #pragma unroll
                for (int j = 0; j < 8; ++j)
                    acc[i][j] = fmaf(a[i], bv[j], acc[i][j]);
        }
    }

    int irow[8], jcol[8];
    #pragma unroll
    for (int i = 0; i < 8; ++i)
        irow[i] = ib + ((i < 4) ? (ty << 2) + i : 64 + (ty << 2) + (i - 4));
    #pragma unroll
    for (int j = 0; j < 8; ++j)
        jcol[j] = jb + ((j < 4) ? (tx << 2) + j : 64 + (tx << 2) + (j - 4));

    float sqi[8], sqj[8];
    #pragma unroll
    for (int i = 0; i < 8; ++i) sqi[i] = g_sq[b * NN + irow[i]];
    #pragma unroll
    for (int j = 0; j < 8; ++j) sqj[j] = g_sq[b * NN + jcol[j]];

    #pragma unroll
    for (int i = 0; i < 8; ++i) {
        float* dst = g_pd + ((size_t)(b * NN + irow[i])) * NN;
        float4 v0, v1;
        v0.x = __fsub_rn(__fsub_rn(__fmul_rn(2.f, acc[i][0]), sqi[i]), sqj[0]);
        v0.y = __fsub_rn(__fsub_rn(__fmul_rn(2.f, acc[i][1]), sqi[i]), sqj[1]);
        v0.z = __fsub_rn(__fsub_rn(__fmul_rn(2.f, acc[i][2]), sqi[i]), sqj[2]);
        v0.w = __fsub_rn(__fsub_rn(__fmul_rn(2.f, acc[i][3]), sqi[i]), sqj[3]);
        v1.x = __fsub_rn(__fsub_rn(__fmul_rn(2.f, acc[i][4]), sqi[i]), sqj[4]);
        v1.y = __fsub_rn(__fsub_rn(__fmul_rn(2.f, acc[i][5]), sqi[i]), sqj[5]);
        v1.z = __fsub_rn(__fsub_rn(__fmul_rn(2.f, acc[i][6]), sqi[i]), sqj[6]);
        v1.w = __fsub_rn(__fsub_rn(__fmul_rn(2.f, acc[i][7]), sqi[i]), sqj[7]);
        *(float4*)&dst[jcol[0]] = v0;
        *(float4*)&dst[jcol[4]] = v1;
    }
}

// ---------------------------------------------------------------------------
// Top-k (k=20) per row, one warp per row. Exactly replicates jax:
//   mn = min over all columns of raw pd;  masked columns := mn;
//   stable top_k (value desc, ties -> lowest index).
// ---------------------------------------------------------------------------
__global__ void __launch_bounds__(256) topk_kernel(const void* __restrict__ locraw) {
    int gw   = (blockIdx.x * blockDim.x + threadIdx.x) >> 5;  // row id
    int lane = threadIdx.x & 31;
    if (gw >= BB * NN) return;
    int b = gw >> 12;

    const float* row = g_pd + (size_t)gw * NN;
    int mode = g_boolmode;
    const unsigned char* loc8  = (const unsigned char*)locraw + b * NN;
    const int*           loc32 = (const int*)locraw + b * NN;

    // pass 1: row min over raw pd (min is order-independent for non-NaN)
    float mn = 3.402823466e38f;
    for (int t = 0; t < NN / 32; ++t)
        mn = fminf(mn, row[t * 32 + lane]);
    #pragma unroll
    for (int o = 16; o; o >>= 1)
        mn = fminf(mn, __shfl_xor_sync(0xffffffffu, mn, o));

    // pass 2: per-lane top-20 over masked values
    float vals[KTOP];
    int   inds[KTOP];
    #pragma unroll
    for (int p = 0; p < KTOP; ++p) { vals[p] = -3.402823466e38f; inds[p] = 0x7fffffff; }

    for (int t = 0; t < NN / 32; ++t) {
        int j = t * 32 + lane;
        bool lc = mode ? (loc32[j] != 0) : (loc8[j] != 0);
        float v = lc ? row[j] : mn;
        if (v > vals[KTOP - 1] || (v == vals[KTOP - 1] && j < inds[KTOP - 1])) {
            vals[KTOP - 1] = v; inds[KTOP - 1] = j;
            #pragma unroll
            for (int p = KTOP - 1; p > 0; --p) {
                bool sw = (vals[p] > vals[p - 1]) ||
                          (vals[p] == vals[p - 1] && inds[p] < inds[p - 1]);
                if (sw) {
                    float tv = vals[p]; vals[p] = vals[p - 1]; vals[p - 1] = tv;
                    int   ti = inds[p]; inds[p] = inds[p - 1]; inds[p - 1] = ti;
                }
            }
        }
    }

    // merge: 20 rounds of warp arg-best over lane heads
    for (int r = 0; r < KTOP; ++r) {
        float bv = vals[0];
        int   bi = inds[0];
        #pragma unroll
        for (int o = 16; o; o >>= 1) {
            float ov = __shfl_xor_sync(0xffffffffu, bv, o);
            int   oi = __shfl_xor_sync(0xffffffffu, bi, o);
            if (ov > bv || (ov == bv && oi < bi)) { bv = ov; bi = oi; }
        }
        if (lane == 0) g_idx[gw * KTOP + r] = bi;
        if (bi == inds[0]) {                 // indices unique -> exactly one winner
            #pragma unroll
            for (int p = 0; p < KTOP - 1; ++p) { vals[p] = vals[p + 1]; inds[p] = inds[p + 1]; }
            vals[KTOP - 1] = -3.402823466e38f;
            inds[KTOP - 1] = 0x7fffffff;
        }
    }
}

// ---------------------------------------------------------------------------
// Per-point local self-attention over k=20 neighbors; one warp per point.
// output[c] = sum_j w[j]*knn[j][c] with w[j] = mean_i attn[i][j] (mean commuted)
// ---------------------------------------------------------------------------
__global__ void __launch_bounds__(128) attn_kernel() {
    __shared__ float s_knn[4][KTOP][68];
    __shared__ float s_sc [4][KTOP][21];
    __shared__ float s_w  [4][KTOP];
    __shared__ int   s_id [4][KTOP];

    int w = threadIdx.x >> 5, lane = threadIdx.x & 31;
    int p = blockIdx.x * 4 + w;
    int b = p >> 12;

    if (lane < KTOP) s_id[w][lane] = g_idx[p * KTOP + lane];
    __syncwarp();

    for (int r = 0; r < KTOP; ++r) {
        int id = s_id[w][r];
        const float* src = g_xt + ((size_t)(b * NN + id)) * CC;
        s_knn[w][r][lane]      = src[lane];
        s_knn[w][r][lane + 32] = src[lane + 32];
    }
    __syncwarp();

    const float scale = 0.125f;   // 1/sqrt(64)
    for (int t = 0; t < 13; ++t) {
        int q = lane + t * 32;
        if (q < KTOP * KTOP) {
            int i = q / KTOP, j = q % KTOP;
            float s = 0.f;
            #pragma unroll
            for (int c = 0; c < CC; ++c)
                s = fmaf(s_knn[w][i][c], s_knn[w][j][c], s);
            s_sc[w][i][j] = s * scale;
        }
    }
    __syncwarp();

    if (lane < KTOP) {
        float m = -3.402823466e38f;
        #pragma unroll
        for (int j = 0; j < KTOP; ++j) m = fmaxf(m, s_sc[w][lane][j]);
        float e[KTOP];
        float sum = 0.f;
        #pragma unroll
        for (int j = 0; j < KTOP; ++j) { e[j] = expf(s_sc[w][lane][j] - m); sum += e[j]; }
        float inv = 1.f / sum;
        #pragma unroll
        for (int j = 0; j < KTOP; ++j) s_sc[w][lane][j] = e[j] * inv;
    }
    __syncwarp();

    if (lane < KTOP) {
        float a = 0.f;
        #pragma unroll
        for (int i = 0; i < KTOP; ++i) a += s_sc[w][i][lane];
        s_w[w][lane] = a * (1.f / (float)KTOP);
    }
    __syncwarp();

    float acc0 = 0.f, acc1 = 0.f;
    #pragma unroll
    for (int j = 0; j < KTOP; ++j) {
        float wj = s_w[w][j];
        acc0 = fmaf(wj, s_knn[w][j][lane],      acc0);
        acc1 = fmaf(wj, s_knn[w][j][lane + 32], acc1);
    }
    g_att[(size_t)p * CC + lane]      = acc0;
    g_att[(size_t)p * CC + lane + 32] = acc1;
}

// ---------------------------------------------------------------------------
// Feature assembly: feature (B, 2C, N, k) + idx_flat appended as float.
// One warp per point; kk-contiguous 80B stores coalesce across adjacent n.
// ---------------------------------------------------------------------------
__global__ void __launch_bounds__(128) feat_kernel(float* __restrict__ out) {
    __shared__ float sg [4][KTOP][68];
    __shared__ float sx [4][CC];
    __shared__ int   sid[4][KTOP];

    const size_t FEAT = (size_t)BB * 2 * CC * NN * KTOP;

    int w = threadIdx.x >> 5, lane = threadIdx.x & 31;
    int p = blockIdx.x * 4 + w;
    int b = p >> 12, n = p & (NN - 1);

    if (lane < KTOP) sid[w][lane] = g_idx[p * KTOP + lane];
    __syncwarp();

    sx[w][lane]      = g_xt[(size_t)p * CC + lane];
    sx[w][lane + 32] = g_xt[(size_t)p * CC + lane + 32];

    for (int r = 0; r < KTOP; ++r) {
        int id = sid[w][r];
        const float* src = g_att + ((size_t)(b * NN + id)) * CC;
        sg[w][r][lane]      = src[lane];
        sg[w][r][lane + 32] = src[lane + 32];
    }
    __syncwarp();

    if (lane < KTOP) {
        #pragma unroll 8
        for (int c2 = 0; c2 < 2 * CC; ++c2) {
            float v = (c2 < CC) ? (sg[w][lane][c2] - sx[w][c2]) : sx[w][c2 - CC];
            out[(((size_t)(b * 2 * CC + c2)) * NN + n) * KTOP + lane] = v;
        }
        out[FEAT + (size_t)p * KTOP + lane] = (float)(sid[w][lane] + b * NN);
    }
}

// ---------------------------------------------------------------------------
extern "C" void kernel_launch(void* const* d_in, const int* in_sizes, int n_in,
                              void* d_out, int out_size) {
    (void)in_sizes; (void)n_in; (void)out_size;
    const float* x  = (const float*)d_in[0];
    const void* loc = d_in[1];          // bool mask (packing auto-detected)
    float* out = (float*)d_out;

    detect_bool_kernel<<<1, 256>>>((const unsigned char*)loc);
    transpose_kernel<<<dim3(NN / 32, CC / 32, BB), dim3(32, 8)>>>(x);
    sq_kernel<<<(BB * NN * 32) / 256, 256>>>(x);
    gemm_kernel<<<dim3(NN / 128, NN / 128, BB), 256>>>(x);
    topk_kernel<<<(BB * NN * 32) / 256, 256>>>(loc);
    attn_kernel<<<(BB * NN) / 4, 128>>>();
    feat_kernel<<<(BB * NN) / 4, 128>>>(out);
}

// round 5
// speedup vs baseline: 1.0383x; 1.0383x over previous
#include <cuda_runtime.h>

#define BB 4
#define CC 64
#define NN 4096
#define KTOP 20
#define NEG (-3.402823466e38f)

// ---- scratch (static __device__ globals; runtime allocation is forbidden) ----
__device__ float g_xt[BB * NN * CC];                 // (B,N,C)  4 MB
__device__ float g_sq[BB * NN];                      // ||x||^2
__device__ int   g_idx[BB * NN * KTOP];              // top-k indices
__device__ float g_att[BB * NN * CC];                // attention output (B,N,C)
__device__ int   g_M[BB * KTOP];                     // 20 smallest non-local idx per batch
__device__ int   g_boolmode;                         // 0 = 1-byte bool, 1 = int32

// ---------------------------------------------------------------------------
// Detect how the bool mask is packed (1-byte bool vs int32). Deterministic.
// ---------------------------------------------------------------------------
__global__ void detect_bool_kernel(const unsigned char* __restrict__ loc) {
    __shared__ int s;
    if (threadIdx.x == 0) s = 0;
    __syncthreads();
    int any = 0;
    for (int i = threadIdx.x; i < BB * NN; i += blockDim.x)
        if ((i & 3) != 0 && loc[i] != 0) any = 1;
    if (any) atomicOr(&s, 1);
    __syncthreads();
    if (threadIdx.x == 0) g_boolmode = s ? 0 : 1;
}

// ---------------------------------------------------------------------------
// g_M[b][0..19] = the 20 smallest non-local indices of batch b (value-free:
// masked columns all take the row-min, so only their indices matter).
// One warp per batch.
// ---------------------------------------------------------------------------
__global__ void prep_M_kernel(const void* __restrict__ locraw) {
    int b = threadIdx.x >> 5, lane = threadIdx.x & 31;
    if (b >= BB) return;
    int mode = g_boolmode;
    const unsigned char* loc8  = (const unsigned char*)locraw + b * NN;
    const int*           loc32 = (const int*)locraw + b * NN;
    if (lane < KTOP) g_M[b * KTOP + lane] = 0x7fffffff;
    __syncwarp();
    int count = 0;
    for (int base = 0; base < NN && count < KTOP; base += 32) {
        int j = base + lane;
        bool nl = mode ? (loc32[j] == 0) : (loc8[j] == 0);
        unsigned bal = __ballot_sync(0xffffffffu, nl);
        if (nl) {
            int pos = __popc(bal & ((1u << lane) - 1));
            if (count + pos < KTOP) g_M[b * KTOP + count + pos] = j;
        }
        count += __popc(bal);
    }
}

// ---------------------------------------------------------------------------
// Transpose x (B,C,N) -> g_xt (B,N,C)   (needed for attn gathers)
// ---------------------------------------------------------------------------
__global__ void transpose_kernel(const float* __restrict__ x) {
    __shared__ float tile[32][33];
    int b = blockIdx.z, c0 = blockIdx.y * 32, n0 = blockIdx.x * 32;
    #pragma unroll
    for (int i = threadIdx.y; i < 32; i += 8)
        tile[i][threadIdx.x] =
            x[((size_t)(b * CC + c0 + i)) * NN + n0 + threadIdx.x];
    __syncthreads();
    #pragma unroll
    for (int i = threadIdx.y; i < 32; i += 8)
        g_xt[((size_t)(b * NN + n0 + i)) * CC + c0 + threadIdx.x] =
            tile[threadIdx.x][i];
}

// ---------------------------------------------------------------------------
// sq: FROZEN — bitwise-matches XLA column-reduce tree (R4 pass depends on it).
// ---------------------------------------------------------------------------
__global__ void sq_kernel(const float* __restrict__ x) {
    int gw   = (blockIdx.x * blockDim.x + threadIdx.x) >> 5;
    int lane = threadIdx.x & 31;
    if (gw >= BB * NN) return;
    int b = gw >> 12;
    int n = gw & (NN - 1);
    const float* xb = x + (size_t)b * CC * NN + n;

    float v0 = xb[(size_t)lane * NN];
    float v1 = xb[(size_t)(lane + 32) * NN];
    float p  = __fadd_rn(__fmul_rn(v0, v0), __fmul_rn(v1, v1));
    p = __fadd_rn(p, __shfl_down_sync(0xffffffffu, p, 16));
    p = __fadd_rn(p, __shfl_down_sync(0xffffffffu, p, 8));
    p = __fadd_rn(p, __shfl_down_sync(0xffffffffu, p, 4));
    p = __fadd_rn(p, __shfl_down_sync(0xffffffffu, p, 2));
    p = __fadd_rn(p, __shfl_down_sync(0xffffffffu, p, 1));
    if (lane == 0) g_sq[gw] = p;
}

// ---------------------------------------------------------------------------
// FUSED pairwise-distance GEMM + top-k. No pd materialization.
// Block: 64 rows x all 4096 cols (32 j-tiles of 128). 256 threads,
// thread tile 4x8. fma chain: k0 in {0,32}, kk ascending, single acc —
// IDENTICAL association to the R4-passing kernel. Epilogue rounding frozen.
// Top-k: per half-warp (owns 4 rows), lexicographic top-20 over LOCAL
// columns in smem + running raw row-min; final merge with (mn, g_M[b][*]).
// ---------------------------------------------------------------------------
__global__ void __launch_bounds__(256) gemmtopk_kernel(const float* __restrict__ x,
                                                       const void* __restrict__ locraw) {
    __shared__ float As[64][64];          // [c][i]  16 KB (persistent)
    __shared__ float Bs[32][128];         // [c][j]  16 KB (per K-chunk)
    __shared__ float s_vals[64][KTOP];    // 5 KB
    __shared__ int   s_inds[64][KTOP];    // 5 KB
    __shared__ float s_mn[64];
    __shared__ float s_sqj[128];
    __shared__ int   s_M[KTOP];
    __shared__ unsigned char s_loc[128];

    int b  = blockIdx.y;
    int i0 = blockIdx.x << 6;
    int tid = threadIdx.x;
    int tx = tid & 15, ty = tid >> 4;
    int lane = tid & 31;
    unsigned hm = (lane < 16) ? 0x0000FFFFu : 0xFFFF0000u;

    const float* xb = x + (size_t)b * CC * NN;
    int mode = g_boolmode;
    const unsigned char* loc8  = (const unsigned char*)locraw + b * NN;
    const int*           loc32 = (const int*)locraw + b * NN;

    // init lists
    for (int e = tid; e < 64 * KTOP; e += 256) {
        ((float*)s_vals)[e] = NEG;
        ((int*)s_inds)[e]   = 0x7fffffff;
    }
    if (tid < 64) s_mn[tid] = 3.402823466e38f;
    if (tid < KTOP) s_M[tid] = g_M[b * KTOP + tid];

    // load As (64x64), persistent for the whole block
    #pragma unroll
    for (int u = 0; u < 4; ++u) {
        int idx = tid + (u << 8);
        int c = idx >> 4, p = (idx & 15) << 2;
        *(float4*)&As[c][p] = *(const float4*)&xb[(size_t)c * NN + i0 + p];
    }

    // per-thread row info
    float sqi[4];
    #pragma unroll
    for (int r = 0; r < 4; ++r) sqi[r] = g_sq[b * NN + i0 + (ty << 2) + r];
    int jcl[8];   // local (within-tile) column offsets
    #pragma unroll
    for (int k = 0; k < 8; ++k)
        jcl[k] = (k < 4) ? ((tx << 2) + k) : (64 + (tx << 2) + (k - 4));

    __syncthreads();

    for (int j0 = 0; j0 < NN; j0 += 128) {
        // (A) previous tile's topk phase done before overwriting s_loc/Bs
        __syncthreads();
        if (tid < 128) {
            int j = j0 + tid;
            s_loc[tid] = mode ? (unsigned char)(loc32[j] != 0)
                              : (unsigned char)(loc8[j] != 0);
            s_sqj[tid] = g_sq[b * NN + j];
        }

        float acc[4][8];
        #pragma unroll
        for (int r = 0; r < 4; ++r)
            #pragma unroll
            for (int k = 0; k < 8; ++k) acc[r][k] = 0.f;

        for (int k0 = 0; k0 < CC; k0 += 32) {
            if (k0) __syncthreads();      // chunk-0 readers done before reload
            #pragma unroll
            for (int u = 0; u < 4; ++u) {
                int idx = tid + (u << 8);
                int c = idx >> 5, p = (idx & 31) << 2;
                *(float4*)&Bs[c][p] = *(const float4*)&xb[(size_t)(k0 + c) * NN + j0 + p];
            }
            __syncthreads();
            #pragma unroll
            for (int kk = 0; kk < 32; ++kk) {
                float4 av = *(float4*)&As[k0 + kk][ty << 2];
                float4 b0 = *(float4*)&Bs[kk][tx << 2];
                float4 b1 = *(float4*)&Bs[kk][64 + (tx << 2)];
                float a[4]  = {av.x, av.y, av.z, av.w};
                float bb[8] = {b0.x, b0.y, b0.z, b0.w, b1.x, b1.y, b1.z, b1.w};
                #pragma unroll
                for (int r = 0; r < 4; ++r)
                    #pragma unroll
                    for (int k = 0; k < 8; ++k)
                        acc[r][k] = fmaf(a[r], bb[k], acc[r][k]);
            }
        }
        __syncthreads();   // all kk reads of Bs done; epilogue reads s_loc/s_sqj

        // epilogue + topk, per half-warp (rows ty*4 .. ty*4+3)
        #pragma unroll
        for (int r = 0; r < 4; ++r) {
            int row = (ty << 2) + r;
            float v[8], cv[8];
            #pragma unroll
            for (int k = 0; k < 8; ++k) {
                v[k] = __fsub_rn(__fsub_rn(__fmul_rn(2.f, acc[r][k]), sqi[r]),
                                 s_sqj[jcl[k]]);
                cv[k] = s_loc[jcl[k]] ? v[k] : NEG;
            }
            // raw row-min over all 8 (matches reference min over all columns)
            float rmin = v[0];
            #pragma unroll
            for (int k = 1; k < 8; ++k) rmin = fminf(rmin, v[k]);
            #pragma unroll
            for (int o = 8; o; o >>= 1)
                rmin = fminf(rmin, __shfl_xor_sync(hm, rmin, o, 16));
            if (tx == 0) s_mn[row] = fminf(s_mn[row], rmin);

            // insert loop: repeatedly extract half-warp lexicographic max
            for (;;) {
                float mybv = cv[0]; int mysl = 0;
                #pragma unroll
                for (int k = 1; k < 8; ++k)
                    if (cv[k] > mybv ||
                        (cv[k] == mybv && jcl[k] < jcl[mysl])) { mybv = cv[k]; mysl = k; }
                int mybi = j0 + jcl[mysl];
                float bv = mybv; int bi = mybi;
                #pragma unroll
                for (int o = 8; o; o >>= 1) {
                    float ov = __shfl_xor_sync(hm, bv, o, 16);
                    int   oi = __shfl_xor_sync(hm, bi, o, 16);
                    if (ov > bv || (ov == bv && oi < bi)) { bv = ov; bi = oi; }
                }
                if (bv == NEG) break;
                float thr  = s_vals[row][KTOP - 1];
                int   thri = s_inds[row][KTOP - 1];
                if (!(bv > thr || (bv == thr && bi < thri))) break;
                if (tx == 0) {   // serial sorted insert
                    int pos = KTOP - 1;
                    #pragma unroll
                    for (int p = KTOP - 1; p > 0; --p) {
                        float pv = s_vals[row][p - 1]; int pi = s_inds[row][p - 1];
                        if (bv > pv || (bv == pv && bi < pi)) {
                            s_vals[row][p] = pv; s_inds[row][p] = pi; pos = p - 1;
                        }
                    }
                    s_vals[row][pos] = bv; s_inds[row][pos] = bi;
                }
                __syncwarp(hm);
                if (bv == mybv && bi == mybi) cv[mysl] = NEG;  // unique winner
            }
        }
    }

    __syncthreads();
    // final merge: local top-20 vs (mn, M[0..19]); one thread per row
    if (tid < 64) {
        int row = tid;
        float mn = s_mn[row];
        int* dst = g_idx + (size_t)(b * NN + i0 + row) * KTOP;
        int pa = 0, pb = 0;
        #pragma unroll
        for (int r = 0; r < KTOP; ++r) {
            float va = s_vals[row][pa]; int ia = s_inds[row][pa];
            int   ib = s_M[pb];
            float vb = (ib == 0x7fffffff) ? NEG : mn;
            bool tA = (va > vb) || (va == vb && ia < ib);
            dst[r] = tA ? ia : ib;
            if (tA) ++pa; else ++pb;
        }
    }
}

// ---------------------------------------------------------------------------
// Per-point local self-attention over k=20 neighbors; one warp per point.
// (unchanged — numerics frozen)
// ---------------------------------------------------------------------------
__global__ void __launch_bounds__(128) attn_kernel() {
    __shared__ float s_knn[4][KTOP][68];
    __shared__ float s_sc [4][KTOP][21];
    __shared__ float s_w  [4][KTOP];
    __shared__ int   s_id [4][KTOP];

    int w = threadIdx.x >> 5, lane = threadIdx.x & 31;
    int p = blockIdx.x * 4 + w;
    int b = p >> 12;

    if (lane < KTOP) s_id[w][lane] = g_idx[p * KTOP + lane];
    __syncwarp();

    for (int r = 0; r < KTOP; ++r) {
        int id = s_id[w][r];
        const float* src = g_xt + ((size_t)(b * NN + id)) * CC;
        s_knn[w][r][lane]      = src[lane];
        s_knn[w][r][lane + 32] = src[lane + 32];
    }
    __syncwarp();

    const float scale = 0.125f;   // 1/sqrt(64)
    for (int t = 0; t < 13; ++t) {
        int q = lane + t * 32;
        if (q < KTOP * KTOP) {
            int i = q / KTOP, j = q % KTOP;
            float s = 0.f;
            #pragma unroll
            for (int c = 0; c < CC; ++c)
                s = fmaf(s_knn[w][i][c], s_knn[w][j][c], s);
            s_sc[w][i][j] = s * scale;
        }
    }
    __syncwarp();

    if (lane < KTOP) {
        float m = NEG;
        #pragma unroll
        for (int j = 0; j < KTOP; ++j) m = fmaxf(m, s_sc[w][lane][j]);
        float e[KTOP];
        float sum = 0.f;
        #pragma unroll
        for (int j = 0; j < KTOP; ++j) { e[j] = expf(s_sc[w][lane][j] - m); sum += e[j]; }
        float inv = 1.f / sum;
        #pragma unroll
        for (int j = 0; j < KTOP; ++j) s_sc[w][lane][j] = e[j] * inv;
    }
    __syncwarp();

    if (lane < KTOP) {
        float a = 0.f;
        #pragma unroll
        for (int i = 0; i < KTOP; ++i) a += s_sc[w][i][lane];
        s_w[w][lane] = a * (1.f / (float)KTOP);
    }
    __syncwarp();

    float acc0 = 0.f, acc1 = 0.f;
    #pragma unroll
    for (int j = 0; j < KTOP; ++j) {
        float wj = s_w[w][j];
        acc0 = fmaf(wj, s_knn[w][j][lane],      acc0);
        acc1 = fmaf(wj, s_knn[w][j][lane + 32], acc1);
    }
    g_att[(size_t)p * CC + lane]      = acc0;
    g_att[(size_t)p * CC + lane + 32] = acc1;
}

// ---------------------------------------------------------------------------
// Feature assembly v2: block = 64 points, att gathers staged through smem in
// 8-channel chunks (g_att is 4 MB -> L2-resident), stores fully coalesced:
// per (c2) a contiguous run of 1280 floats.
// ---------------------------------------------------------------------------
__global__ void __launch_bounds__(256) feat_kernel(const float* __restrict__ x,
                                                   float* __restrict__ out) {
    __shared__ int   s_nb[64 * KTOP];       // 5 KB
    __shared__ float s_att[64 * KTOP][8];   // 40 KB
    __shared__ float s_x[8][64];            // 2 KB

    int b  = blockIdx.y;
    int n0 = blockIdx.x << 6;
    int tid = threadIdx.x;

    for (int e = tid; e < 64 * KTOP; e += 256)
        s_nb[e] = g_idx[((size_t)(b * NN + n0)) * KTOP + e];
    __syncthreads();

    const float* attb = g_att + (size_t)b * NN * CC;
    const float* xb   = x + (size_t)b * CC * NN;
    const size_t outb = ((size_t)b * 2 * CC) * NN * KTOP;

    for (int c0 = 0; c0 < 2 * CC; c0 += 8) {
        __syncthreads();                      // prev chunk readers done
        bool firstHalf = (c0 < CC);
        int cx = firstHalf ? c0 : (c0 - CC);
        for (int e = tid; e < 8 * 64; e += 256) {
            int r = e >> 6, p = e & 63;
            s_x[r][p] = xb[(size_t)(cx + r) * NN + n0 + p];
        }
        if (firstHalf) {
            for (int e = tid; e < 64 * KTOP; e += 256) {
                int nb = s_nb[e];
                const float* src = attb + (size_t)nb * CC + c0;
                *(float4*)&s_att[e][0] = *(const float4*)(src);
                *(float4*)&s_att[e][4] = *(const float4*)(src + 4);
            }
        }
        __syncthreads();
        #pragma unroll
        for (int cc = 0; cc < 8; ++cc) {
            int c2 = c0 + cc;
            float* dst = out + outb + ((size_t)c2 * NN + n0) * KTOP;
            for (int e = tid; e < 64 * KTOP; e += 256) {
                int dn = e / KTOP;
                float v = firstHalf ? (s_att[e][cc] - s_x[cc][dn]) : s_x[cc][dn];
                dst[e] = v;
            }
        }
    }

    // idx_flat tail
    const size_t FEAT = (size_t)BB * 2 * CC * NN * KTOP;
    for (int e = tid; e < 64 * KTOP; e += 256)
        out[FEAT + ((size_t)(b * NN + n0)) * KTOP + e] = (float)(s_nb[e] + b * NN);
}

// ---------------------------------------------------------------------------
extern "C" void kernel_launch(void* const* d_in, const int* in_sizes, int n_in,
                              void* d_out, int out_size) {
    (void)in_sizes; (void)n_in; (void)out_size;
    const float* x  = (const float*)d_in[0];
    const void* loc = d_in[1];          // bool mask (packing auto-detected)
    float* out = (float*)d_out;

    detect_bool_kernel<<<1, 256>>>((const unsigned char*)loc);
    prep_M_kernel<<<1, 128>>>(loc);
    transpose_kernel<<<dim3(NN / 32, CC / 32, BB), dim3(32, 8)>>>(x);
    sq_kernel<<<(BB * NN * 32) / 256, 256>>>(x);
    gemmtopk_kernel<<<dim3(NN / 64, BB), 256>>>(x, loc);
    attn_kernel<<<(BB * NN) / 4, 128>>>();
    feat_kernel<<<dim3(NN / 64, BB), 256>>>(x, out);
}